// round 13
// baseline (speedup 1.0000x reference)
#include <cuda_runtime.h>

// AffineTransformation: B=32, H=W=512, C=1, fp32.
// d_in[0] = theta [32,6] f32, d_in[1] = image [32,512,512,1] f32 -> out same shape.
//
// R11 core (2D warp patches, scalar gathers, 16 batched LDGs) + ADAPTIVE PATCH
// SHAPE: warp-gather cost = image rows spanned = (a-1)|t3| + (b-1)|t4| for an
// a x b lane patch. Per batch (uniform branch) pick 8x4 when |t3| <= |t4|,
// else 4x8 -> expected row-span drops ~24% vs fixed 8x4. Tile decode is also
// reshaped per batch (32x16 vs 16x32) from the same 512-tile linear id.

#define BB 32
#define HH 512
#define WW 512

__global__ __launch_bounds__(128, 10)
void affine_sample_kernel(const float* __restrict__ theta,
                          const float* __restrict__ image,
                          float* __restrict__ out)
{
    const int b = blockIdx.z;

    const float t0 = __ldg(theta + b * 6 + 0);
    const float t1 = __ldg(theta + b * 6 + 1);
    const float t2 = __ldg(theta + b * 6 + 2);
    const float t3 = __ldg(theta + b * 6 + 3);
    const float t4 = __ldg(theta + b * 6 + 4);
    const float t5 = __ldg(theta + b * 6 + 5);

    const int warp = threadIdx.x >> 5;
    const int lane = threadIdx.x & 31;

    // Patch shape (uniform per batch): minimize (a-1)|t3| + (b-1)|t4|
    const bool wide = fabsf(t3) <= fabsf(t4);   // true -> 8x4 lanes, else 4x8

    const int tid = blockIdx.y * 16 + blockIdx.x;   // linear tile id 0..511

    int col, row0, jstep;
    if (wide) {
        // tiles 32x16: 16 col-tiles x 32 row-tiles
        const int tcx = tid & 15, tcy = tid >> 4;
        const int lx = lane & 7, ly = lane >> 3;        // 8x4 patch
        col   = tcx * 32 + warp * 8 + lx;
        row0  = tcy * 16 + ly;                          // rows row0 + 4j
        jstep = 4;
    } else {
        // tiles 16x32: 32 col-tiles x 16 row-tiles
        const int tcx = tid & 31, tcy = tid >> 5;
        const int lx = lane & 3, ly = lane >> 2;        // 4x8 patch
        col   = tcx * 16 + warp * 4 + lx;
        row0  = tcy * 32 + ly;                          // rows row0 + 8j
        jstep = 8;
    }

    const float inv_w = 2.0f / (float)(WW - 1);
    const float inv_h = 2.0f / (float)(HH - 1);
    const float xn  = -1.0f + (float)col  * inv_w;
    const float yn0 = -1.0f + (float)row0 * inv_h;

    // Pixel-space coords at j=0. Per-j step = jstep screen rows.
    const float fx0 = 0.5f * (float)(WW - 1) * (t0 * xn + t1 * yn0 + t2) + 0.5f * (float)(WW - 1);
    const float fy0 = 0.5f * (float)(HH - 1) * (t3 * xn + t4 * yn0 + t5) + 0.5f * (float)(HH - 1);
    const float sjx = (float)jstep * t1;
    const float sjy = (float)jstep * t4;
    const float fx3 = fmaf(3.0f, sjx, fx0);
    const float fy3 = fmaf(3.0f, sjy, fy0);

    const float lox = fminf(fx0, fx3), hix = fmaxf(fx0, fx3);
    const float loy = fminf(fy0, fy3), hiy = fmaxf(fy0, fy3);

    float* const op = out + (b * HH + row0) * WW + col;   // int32-safe
    const int ostep = jstep * WW;

    // (c) whole span has zero coverage -> store zeros, no gathers
    if (hix <= -1.0f || lox >= (float)WW || hiy <= -1.0f || loy >= (float)HH) {
        #pragma unroll
        for (int j = 0; j < 4; j++) op[j * ostep] = 0.0f;
        return;
    }

    const float* __restrict__ img = image + b * (HH * WW);

    float r[4];

    if (lox >= 0.0f && hix < (float)(WW - 1) && loy >= 0.0f && hiy < (float)(HH - 1)) {
        // (a) fully interior: trunc == floor, plain bilinear lerp.
        // Phase 1: addresses + fractions. Phase 2: all 16 LDGs. Phase 3: math.
        float ax[4], ay[4];
        int   base[4];
        #pragma unroll
        for (int j = 0; j < 4; j++) {
            const float fx = fmaf((float)j, sjx, fx0);
            const float fy = fmaf((float)j, sjy, fy0);
            const int ix = (int)fx;
            const int iy = (int)fy;
            ax[j] = fx - (float)ix;
            ay[j] = fy - (float)iy;
            base[j] = iy * WW + ix;
        }
        float va[4], vb[4], vc[4], vd[4];
        #pragma unroll
        for (int j = 0; j < 4; j++) {
            va[j] = __ldg(img + base[j]);
            vb[j] = __ldg(img + base[j] + 1);
            vc[j] = __ldg(img + base[j] + WW);
            vd[j] = __ldg(img + base[j] + WW + 1);
        }
        #pragma unroll
        for (int j = 0; j < 4; j++) {
            const float h0 = fmaf(ax[j], vb[j] - va[j], va[j]);
            const float h1 = fmaf(ax[j], vd[j] - vc[j], vc[j]);
            r[j] = __saturatef(fmaf(ay[j], h1 - h0, h0));
        }
    } else {
        // (b) border: full reference semantics (clip-then-delta, edge double-count)
        #pragma unroll
        for (int j = 0; j < 4; j++) {
            const float fx = fmaf((float)j, sjx, fx0);
            const float fy = fmaf((float)j, sjy, fy0);

            const float flx = floorf(fx);
            const float fly = floorf(fy);

            const float x0 = fminf(fmaxf(flx,        0.0f), (float)(WW - 1));
            const float x1 = fminf(fmaxf(flx + 1.0f, 0.0f), (float)(WW - 1));
            const float y0 = fminf(fmaxf(fly,        0.0f), (float)(HH - 1));
            const float y1 = fminf(fmaxf(fly + 1.0f, 0.0f), (float)(HH - 1));

            const float wx0 = fmaxf(0.0f, 1.0f - fabsf(fx - x0));
            const float wx1 = fmaxf(0.0f, 1.0f - fabsf(fx - x1));
            const float wy0 = fmaxf(0.0f, 1.0f - fabsf(fy - y0));
            const float wy1 = fmaxf(0.0f, 1.0f - fabsf(fy - y1));

            float v = 0.0f;
            if ((wx0 + wx1) > 0.0f && (wy0 + wy1) > 0.0f) {
                const int ix0 = (int)x0;
                const int ix1 = (int)x1;
                const int r0o = (int)y0 * WW;
                const int r1o = (int)y1 * WW;
                v = wy0 * (wx0 * __ldg(img + r0o + ix0) + wx1 * __ldg(img + r0o + ix1))
                  + wy1 * (wx0 * __ldg(img + r1o + ix0) + wx1 * __ldg(img + r1o + ix1));
            }
            r[j] = __saturatef(v);
        }
    }

    #pragma unroll
    for (int j = 0; j < 4; j++) op[j * ostep] = r[j];
}

extern "C" void kernel_launch(void* const* d_in, const int* in_sizes, int n_in,
                              void* d_out, int out_size)
{
    const float* theta = (const float*)d_in[0];
    const float* image = (const float*)d_in[1];
    float* out = (float*)d_out;

    dim3 block(128, 1, 1);                 // 4 warps
    dim3 grid(16, 32, BB);                 // 512 tiles/batch, decoded per shape
    affine_sample_kernel<<<grid, block>>>(theta, image, out);
}

// round 14
// speedup vs baseline: 1.1100x; 1.1100x over previous
#include <cuda_runtime.h>

// AffineTransformation: B=32, H=W=512, C=1, fp32.
// d_in[0] = theta [32,6] f32, d_in[1] = image [32,512,512,1] f32 -> out same shape.
//
// R11 per-warp geometry (8x4 lane patch, scalar gathers, 16 batched LDGs) with
// 256-thread blocks: 8 warps arranged 4 across x 2 down -> 32x32 px tile.
// Bigger blocks fill warp slots better (R5 measured highest occ at 256 thr);
// more resident warps -> more outstanding gathers into the L1tex pipe, which
// is the measured bottleneck (61-64% busy, latency-limited).

#define BB 32
#define HH 512
#define WW 512

__global__ __launch_bounds__(256, 6)
void affine_sample_kernel(const float* __restrict__ theta,
                          const float* __restrict__ image,
                          float* __restrict__ out)
{
    const int b = blockIdx.z;

    const float t0 = __ldg(theta + b * 6 + 0);
    const float t1 = __ldg(theta + b * 6 + 1);
    const float t2 = __ldg(theta + b * 6 + 2);
    const float t3 = __ldg(theta + b * 6 + 3);
    const float t4 = __ldg(theta + b * 6 + 4);
    const float t5 = __ldg(theta + b * 6 + 5);

    const int warp = threadIdx.x >> 5;      // 0..7
    const int lane = threadIdx.x & 31;
    const int wx   = warp & 3;              // 4 warps across
    const int wyp  = warp >> 2;             // 2 warp rows
    const int lx   = lane & 7;              // col within 8x4 warp patch
    const int ly   = lane >> 3;             // row within warp patch (0..3)

    const int col  = blockIdx.x * 32 + wx * 8 + lx;     // 0..511
    const int row0 = blockIdx.y * 32 + wyp * 16 + ly;   // pixels at row0 + 4j

    const float inv_w = 2.0f / (float)(WW - 1);
    const float inv_h = 2.0f / (float)(HH - 1);
    const float xn  = -1.0f + (float)col  * inv_w;
    const float yn0 = -1.0f + (float)row0 * inv_h;

    // Pixel-space coords at j=0. Per-j step = 4 screen rows: d(fx)=4*t1, d(fy)=4*t4.
    const float fx0 = 0.5f * (float)(WW - 1) * (t0 * xn + t1 * yn0 + t2) + 0.5f * (float)(WW - 1);
    const float fy0 = 0.5f * (float)(HH - 1) * (t3 * xn + t4 * yn0 + t5) + 0.5f * (float)(HH - 1);
    const float sjx = 4.0f * t1;
    const float sjy = 4.0f * t4;
    const float fx3 = fmaf(3.0f, sjx, fx0);
    const float fy3 = fmaf(3.0f, sjy, fy0);

    const float lox = fminf(fx0, fx3), hix = fmaxf(fx0, fx3);
    const float loy = fminf(fy0, fy3), hiy = fmaxf(fy0, fy3);

    float* const op = out + (b * HH + row0) * WW + col;   // int32-safe
    const int ostep = 4 * WW;                             // 4 rows per j

    // (c) whole span has zero coverage -> store zeros, no gathers
    if (hix <= -1.0f || lox >= (float)WW || hiy <= -1.0f || loy >= (float)HH) {
        #pragma unroll
        for (int j = 0; j < 4; j++) op[j * ostep] = 0.0f;
        return;
    }

    const float* __restrict__ img = image + b * (HH * WW);

    float r[4];

    if (lox >= 0.0f && hix < (float)(WW - 1) && loy >= 0.0f && hiy < (float)(HH - 1)) {
        // (a) fully interior: no clamps, trunc == floor, plain bilinear lerp.
        // Phase 1: addresses + fractions. Phase 2: all 16 LDGs. Phase 3: math.
        float ax[4], ay[4];
        int   base[4];
        #pragma unroll
        for (int j = 0; j < 4; j++) {
            const float fx = fmaf((float)j, sjx, fx0);
            const float fy = fmaf((float)j, sjy, fy0);
            const int ix = (int)fx;
            const int iy = (int)fy;
            ax[j] = fx - (float)ix;
            ay[j] = fy - (float)iy;
            base[j] = iy * WW + ix;
        }
        float va[4], vb[4], vc[4], vd[4];
        #pragma unroll
        for (int j = 0; j < 4; j++) {
            va[j] = __ldg(img + base[j]);
            vb[j] = __ldg(img + base[j] + 1);
            vc[j] = __ldg(img + base[j] + WW);
            vd[j] = __ldg(img + base[j] + WW + 1);
        }
        #pragma unroll
        for (int j = 0; j < 4; j++) {
            const float h0 = fmaf(ax[j], vb[j] - va[j], va[j]);
            const float h1 = fmaf(ax[j], vd[j] - vc[j], vc[j]);
            r[j] = __saturatef(fmaf(ay[j], h1 - h0, h0));
        }
    } else {
        // (b) border: full reference semantics (clip-then-delta, edge double-count)
        #pragma unroll
        for (int j = 0; j < 4; j++) {
            const float fx = fmaf((float)j, sjx, fx0);
            const float fy = fmaf((float)j, sjy, fy0);

            const float flx = floorf(fx);
            const float fly = floorf(fy);

            const float x0 = fminf(fmaxf(flx,        0.0f), (float)(WW - 1));
            const float x1 = fminf(fmaxf(flx + 1.0f, 0.0f), (float)(WW - 1));
            const float y0 = fminf(fmaxf(fly,        0.0f), (float)(HH - 1));
            const float y1 = fminf(fmaxf(fly + 1.0f, 0.0f), (float)(HH - 1));

            const float wx0 = fmaxf(0.0f, 1.0f - fabsf(fx - x0));
            const float wx1 = fmaxf(0.0f, 1.0f - fabsf(fx - x1));
            const float wy0 = fmaxf(0.0f, 1.0f - fabsf(fy - y0));
            const float wy1 = fmaxf(0.0f, 1.0f - fabsf(fy - y1));

            float v = 0.0f;
            if ((wx0 + wx1) > 0.0f && (wy0 + wy1) > 0.0f) {
                const int ix0 = (int)x0;
                const int ix1 = (int)x1;
                const int r0o = (int)y0 * WW;
                const int r1o = (int)y1 * WW;
                v = wy0 * (wx0 * __ldg(img + r0o + ix0) + wx1 * __ldg(img + r0o + ix1))
                  + wy1 * (wx0 * __ldg(img + r1o + ix0) + wx1 * __ldg(img + r1o + ix1));
            }
            r[j] = __saturatef(v);
        }
    }

    #pragma unroll
    for (int j = 0; j < 4; j++) op[j * ostep] = r[j];
}

extern "C" void kernel_launch(void* const* d_in, const int* in_sizes, int n_in,
                              void* d_out, int out_size)
{
    const float* theta = (const float*)d_in[0];
    const float* image = (const float*)d_in[1];
    float* out = (float*)d_out;

    dim3 block(256, 1, 1);                 // 8 warps; block tile = 32 x 32 px
    dim3 grid(WW / 32, HH / 32, BB);       // (16, 16, 32) = 8192 blocks
    affine_sample_kernel<<<grid, block>>>(theta, image, out);
}